// round 1
// baseline (speedup 1.0000x reference)
#include <cuda_runtime.h>
#include <cstdint>
#include <cstddef>

// ---------------------------------------------------------------------------
// Problem constants (fixed by the dataset)
// ---------------------------------------------------------------------------
#define N_NODES 50000
#define N_EDGES 1600000
#define NFEAT   512
#define NHID    64
#define H1      8
#define NCLASS  16
#define HCAT    (H1 * NHID)   // 512
#define ALPHA   0.2f

// ---------------------------------------------------------------------------
// Scratch (device globals; no allocation allowed)
// ---------------------------------------------------------------------------
__device__ float g_h1[(size_t)H1 * N_NODES * NHID];     // per-head layer1 features
__device__ float g_hcat[(size_t)N_NODES * HCAT];        // concat(elu(h_prime1))
__device__ float g_h2[(size_t)N_NODES * NCLASS];        // layer2 linear
__device__ float g_p2[(size_t)N_NODES * NCLASS];        // layer2 aggregated
__device__ float g_s1src[H1 * N_NODES];
__device__ float g_s1dst[H1 * N_NODES];
__device__ float g_s2src[N_NODES];
__device__ float g_s2dst[N_NODES];
__device__ int   g_deg[N_NODES];
__device__ int   g_rowptr[N_NODES + 1];
__device__ int   g_fill[N_NODES];
__device__ int   g_dst_sorted[N_EDGES];

// ---------------------------------------------------------------------------
// CSR construction
// ---------------------------------------------------------------------------
__global__ void k_zero_deg() {
    int i = blockIdx.x * blockDim.x + threadIdx.x;
    if (i < N_NODES) g_deg[i] = 0;
}

__global__ void k_degree(const int* __restrict__ ei) {
    int e = blockIdx.x * blockDim.x + threadIdx.x;
    if (e < N_EDGES) atomicAdd(&g_deg[ei[e]], 1);
}

// Single-block exclusive scan over 50000 degrees -> rowptr, fill
__global__ __launch_bounds__(1024) void k_scan() {
    __shared__ int sums[1024];
    int tid = threadIdx.x;
    constexpr int CH = (N_NODES + 1023) / 1024;  // 49
    int start = tid * CH;
    int end = min(start + CH, N_NODES);
    int s = 0;
    for (int i = start; i < end; ++i) s += g_deg[i];
    sums[tid] = s;
    __syncthreads();
    for (int off = 1; off < 1024; off <<= 1) {
        int t = (tid >= off) ? sums[tid - off] : 0;
        __syncthreads();
        sums[tid] += t;
        __syncthreads();
    }
    int running = sums[tid] - s;  // exclusive prefix of this chunk
    for (int i = start; i < end; ++i) {
        g_rowptr[i] = running;
        g_fill[i]   = running;
        running += g_deg[i];
    }
    if (tid == 1023) g_rowptr[N_NODES] = sums[1023];
}

__global__ void k_scatter(const int* __restrict__ ei) {
    int e = blockIdx.x * blockDim.x + threadIdx.x;
    if (e < N_EDGES) {
        int s = ei[e];
        int d = ei[N_EDGES + e];
        int pos = atomicAdd(&g_fill[s], 1);
        g_dst_sorted[pos] = d;
    }
}

// ---------------------------------------------------------------------------
// Tiled SGEMM: C[M,ncols] = A[M,K] @ B[K,ncols]; grid.y = head
// BM=64, BN=64, BK=16, 256 threads, 4x4 microtile.
// ---------------------------------------------------------------------------
__global__ __launch_bounds__(256) void k_sgemm(
    const float* __restrict__ A, const float* __restrict__ Bbase,
    float* __restrict__ Cbase, int M, int K, int ncols,
    long bHeadStride, long cHeadStride)
{
    constexpr int BM = 64, BN = 64, BK = 16;
    __shared__ float As[BK][BM];   // transposed A tile
    __shared__ float Bs[BK][BN];

    int h = blockIdx.y;
    const float* B = Bbase + (size_t)h * bHeadStride;
    float* C = Cbase + (size_t)h * cHeadStride;

    int m0 = blockIdx.x * BM;
    int tid = threadIdx.x;
    int tx = tid & 15, ty = tid >> 4;

    float acc[4][4] = {};

    int aRow = tid >> 2;          // 0..63
    int aCol = (tid & 3) * 4;     // 0,4,8,12
    int bRow = tid >> 4;          // 0..15
    int bCol = (tid & 15) * 4;    // 0..60

    const bool aValid = (m0 + aRow) < M;
    const bool bValid = bCol < ncols;
    const float* Aptr = A + (size_t)(m0 + aRow) * K + aCol;
    const float* Bptr = B + (size_t)bRow * ncols + bCol;

    for (int k0 = 0; k0 < K; k0 += BK) {
        float4 av = aValid ? *(const float4*)(Aptr + k0) : make_float4(0.f, 0.f, 0.f, 0.f);
        float4 bv = bValid ? *(const float4*)(Bptr + (size_t)k0 * ncols) : make_float4(0.f, 0.f, 0.f, 0.f);
        __syncthreads();
        As[aCol + 0][aRow] = av.x;
        As[aCol + 1][aRow] = av.y;
        As[aCol + 2][aRow] = av.z;
        As[aCol + 3][aRow] = av.w;
        *(float4*)&Bs[bRow][bCol] = bv;
        __syncthreads();
#pragma unroll
        for (int k = 0; k < BK; ++k) {
            float4 a4 = *(const float4*)&As[k][ty * 4];
            float4 b4 = *(const float4*)&Bs[k][tx * 4];
            float ar[4] = {a4.x, a4.y, a4.z, a4.w};
            float br[4] = {b4.x, b4.y, b4.z, b4.w};
#pragma unroll
            for (int i = 0; i < 4; ++i)
#pragma unroll
                for (int j = 0; j < 4; ++j)
                    acc[i][j] = fmaf(ar[i], br[j], acc[i][j]);
        }
    }

#pragma unroll
    for (int i = 0; i < 4; ++i) {
        int r = m0 + ty * 4 + i;
        if (r >= M) break;
#pragma unroll
        for (int j = 0; j < 4; ++j) {
            int c = tx * 4 + j;
            if (c < ncols) C[(size_t)r * ncols + c] = acc[i][j];
        }
    }
}

// ---------------------------------------------------------------------------
// Layer-1 attention scores: s_src/s_dst = h1 . a1 parts, warp per (node, head)
// ---------------------------------------------------------------------------
__global__ __launch_bounds__(256) void k_scores1(const float* __restrict__ a1) {
    int warp = threadIdx.x >> 5;
    int lane = threadIdx.x & 31;
    int n = blockIdx.x * 8 + warp;
    int h = blockIdx.y;
    if (n >= N_NODES) return;
    const float* hp = g_h1 + ((size_t)h * N_NODES + n) * NHID;
    float2 hv = *(const float2*)(hp + lane * 2);
    const float* a = a1 + h * (2 * NHID);
    float2 as = *(const float2*)(a + lane * 2);
    float2 ad = *(const float2*)(a + NHID + lane * 2);
    float ps = hv.x * as.x + hv.y * as.y;
    float pd = hv.x * ad.x + hv.y * ad.y;
#pragma unroll
    for (int o = 16; o; o >>= 1) {
        ps += __shfl_xor_sync(0xFFFFFFFFu, ps, o);
        pd += __shfl_xor_sync(0xFFFFFFFFu, pd, o);
    }
    if (lane == 0) {
        g_s1src[h * N_NODES + n] = ps;
        g_s1dst[h * N_NODES + n] = pd;
    }
}

// ---------------------------------------------------------------------------
// Layer-1 CSR aggregation: warp per (node, head); lane holds 2 features.
// Writes elu(agg/rowsum) straight into hcat[n][h*64 + f].
// ---------------------------------------------------------------------------
__global__ __launch_bounds__(256) void k_agg1() {
    int warp = threadIdx.x >> 5;
    int lane = threadIdx.x & 31;
    int n = blockIdx.x * 8 + warp;
    int h = blockIdx.y;
    if (n >= N_NODES) return;
    int beg = g_rowptr[n], end = g_rowptr[n + 1];
    float ssrc = g_s1src[h * N_NODES + n];
    const float* hb = g_h1 + (size_t)h * N_NODES * NHID;
    const float* sd = g_s1dst + (size_t)h * N_NODES;
    float ax = 0.f, ay = 0.f, rs = 0.f;
    for (int i = beg; i < end; ++i) {
        int v = __ldg(&g_dst_sorted[i]);
        float lg = ssrc + __ldg(&sd[v]);
        lg = lg > 0.f ? lg : ALPHA * lg;
        float e = __expf(-lg);
        rs += e;
        float2 hv = *(const float2*)(hb + (size_t)v * NHID + lane * 2);
        ax = fmaf(e, hv.x, ax);
        ay = fmaf(e, hv.y, ay);
    }
    float inv = 1.f / rs;
    float o0 = ax * inv, o1 = ay * inv;
    o0 = o0 > 0.f ? o0 : expm1f(o0);
    o1 = o1 > 0.f ? o1 : expm1f(o1);
    *(float2*)(g_hcat + (size_t)n * HCAT + h * NHID + lane * 2) = make_float2(o0, o1);
}

// ---------------------------------------------------------------------------
// Layer-2 scores (16-dim dots, thread per node)
// ---------------------------------------------------------------------------
__global__ void k_scores2(const float* __restrict__ a2) {
    int n = blockIdx.x * blockDim.x + threadIdx.x;
    if (n >= N_NODES) return;
    float ps = 0.f, pd = 0.f;
    const float* hp = g_h2 + (size_t)n * NCLASS;
#pragma unroll
    for (int c = 0; c < NCLASS; ++c) {
        float v = hp[c];
        ps = fmaf(v, __ldg(&a2[c]), ps);
        pd = fmaf(v, __ldg(&a2[NCLASS + c]), pd);
    }
    g_s2src[n] = ps;
    g_s2dst[n] = pd;
}

// ---------------------------------------------------------------------------
// Layer-2 CSR aggregation: thread per (node, class); 2 nodes per warp.
// ---------------------------------------------------------------------------
__global__ __launch_bounds__(256) void k_agg2() {
    int t = blockIdx.x * blockDim.x + threadIdx.x;
    int n = t >> 4;
    int f = t & 15;
    if (n >= N_NODES) return;
    int beg = g_rowptr[n], end = g_rowptr[n + 1];
    float ss = g_s2src[n];
    float acc = 0.f, rs = 0.f;
    for (int i = beg; i < end; ++i) {
        int v = __ldg(&g_dst_sorted[i]);
        float lg = ss + __ldg(&g_s2dst[v]);
        lg = lg > 0.f ? lg : ALPHA * lg;
        float e = __expf(-lg);
        rs += e;
        acc = fmaf(e, __ldg(&g_h2[(size_t)v * NCLASS + f]), acc);
    }
    g_p2[(size_t)n * NCLASS + f] = acc / rs;
}

// ---------------------------------------------------------------------------
// elu + log_softmax over 16 classes, thread per node
// ---------------------------------------------------------------------------
__global__ void k_final(float* __restrict__ out) {
    int n = blockIdx.x * blockDim.x + threadIdx.x;
    if (n >= N_NODES) return;
    float v[NCLASS];
    float m = -1e30f;
#pragma unroll
    for (int c = 0; c < NCLASS; ++c) {
        float x = g_p2[(size_t)n * NCLASS + c];
        x = x > 0.f ? x : expm1f(x);
        v[c] = x;
        m = fmaxf(m, x);
    }
    float s = 0.f;
#pragma unroll
    for (int c = 0; c < NCLASS; ++c) s += __expf(v[c] - m);
    float l = m + logf(s);
#pragma unroll
    for (int c = 0; c < NCLASS; ++c) out[(size_t)n * NCLASS + c] = v[c] - l;
}

// ---------------------------------------------------------------------------
// Launch
// ---------------------------------------------------------------------------
extern "C" void kernel_launch(void* const* d_in, const int* in_sizes, int n_in,
                              void* d_out, int out_size) {
    const float* x  = (const float*)d_in[0];
    const int*   ei = (const int*)d_in[1];
    const float* W1 = (const float*)d_in[2];
    const float* a1 = (const float*)d_in[3];
    const float* W2 = (const float*)d_in[4];
    const float* a2 = (const float*)d_in[5];
    float* out = (float*)d_out;

    void *h1p = nullptr, *hcatp = nullptr, *h2p = nullptr;
    cudaGetSymbolAddress(&h1p, g_h1);
    cudaGetSymbolAddress(&hcatp, g_hcat);
    cudaGetSymbolAddress(&h2p, g_h2);

    // CSR build
    k_zero_deg<<<(N_NODES + 255) / 256, 256>>>();
    k_degree<<<(N_EDGES + 255) / 256, 256>>>(ei);
    k_scan<<<1, 1024>>>();
    k_scatter<<<(N_EDGES + 255) / 256, 256>>>(ei);

    // Layer 1
    dim3 g1((N_NODES + 63) / 64, H1);
    k_sgemm<<<g1, 256>>>(x, W1, (float*)h1p, N_NODES, NFEAT, NHID,
                         (long)NFEAT * NHID, (long)N_NODES * NHID);
    dim3 gw((N_NODES + 7) / 8, H1);
    k_scores1<<<gw, 256>>>(a1);
    k_agg1<<<gw, 256>>>();

    // Layer 2
    dim3 g2((N_NODES + 63) / 64, 1);
    k_sgemm<<<g2, 256>>>((const float*)hcatp, W2, (float*)h2p, N_NODES, HCAT, NCLASS, 0, 0);
    k_scores2<<<(N_NODES + 255) / 256, 256>>>(a2);
    k_agg2<<<(N_NODES * NCLASS + 255) / 256, 256>>>();
    k_final<<<(N_NODES + 255) / 256, 256>>>(out);
}